// round 3
// baseline (speedup 1.0000x reference)
#include <cuda_runtime.h>
#include <math.h>
#include <stdint.h>

#define L_SEQ 16384
#define H_DIM 128
#define P_DIM 256
#define NSEQ  512          // 256 channels x {re, im}
#define NCHUNK 128
#define CLEN   128         // NCHUNK * CLEN == L_SEQ

// ---------------------------------------------------------------------------
// Scratch (device globals; no allocations allowed)
__device__ float  g_buall[L_SEQ * NSEQ];    // (L, 512) fp32 Bu (for scan passes)
__device__ float  g_x2Phi[L_SEQ * NSEQ];    // x2 tf32-hi, K-permuted (GEMM2 A)
__device__ float  g_x2Plo[L_SEQ * NSEQ];    // x2 residual-lo, K-permuted
__device__ float  g_inPhi[L_SEQ * H_DIM];   // input hi, K-permuted (GEMM1 A)
__device__ float  g_inPlo[L_SEQ * H_DIM];
__device__ float  g_W1Phi[NSEQ * H_DIM];    // [Br;Bi] hi, K-permuted (GEMM1 B)
__device__ float  g_W1Plo[NSEQ * H_DIM];
__device__ float  g_W2Phi[H_DIM * NSEQ];    // [Cr,-Ci] hi, K-permuted (GEMM2 B)
__device__ float  g_W2Plo[H_DIM * NSEQ];
__device__ float2 g_final[NCHUNK * NSEQ];
__device__ float2 g_initv[NCHUNK * NSEQ];

// ---------------------------------------------------------------------------
__device__ __forceinline__ uint32_t f2tf32(float v) {
    uint32_t r;
    asm("cvt.rna.tf32.f32 %0, %1;" : "=r"(r) : "f"(v));
    return r;
}
__device__ __forceinline__ int perm_k(int k) {  // permute within 32-k blocks
    return (k & ~31) | (((k & 3) << 3) | ((k & 31) >> 2));
}
__device__ __forceinline__ void mma_tf32(float* d, uint32_t a0, uint32_t a1,
                                         uint32_t a2, uint32_t a3,
                                         uint32_t b0, uint32_t b1) {
    asm volatile(
        "mma.sync.aligned.m16n8k8.row.col.f32.tf32.tf32.f32 "
        "{%0,%1,%2,%3},{%4,%5,%6,%7},{%8,%9},{%0,%1,%2,%3};\n"
        : "+f"(d[0]), "+f"(d[1]), "+f"(d[2]), "+f"(d[3])
        : "r"(a0), "r"(a1), "r"(a2), "r"(a3), "r"(b0), "r"(b1));
}
#define CP16(dst_u32, src_ptr) \
    asm volatile("cp.async.cg.shared.global [%0], [%1], 16;\n" :: "r"(dst_u32), "l"(src_ptr))

// ---------------------------------------------------------------------------
// Prep: split input into tf32 hi/lo with permuted K layout
__global__ void prep_input(const float* __restrict__ in) {
    int idx = blockIdx.x * blockDim.x + threadIdx.x;   // over L*H
    float v = in[idx];
    float hi = __uint_as_float(f2tf32(v));
    int row = idx >> 7, col = idx & 127;
    int pc = perm_k(col);
    g_inPhi[(row << 7) | pc] = hi;
    g_inPlo[(row << 7) | pc] = v - hi;
}

// Prep: pack + split + permute W1 (512x128) and W2 (128x512)
__global__ void prep_w(const float* __restrict__ B, const float* __restrict__ C) {
    int i = blockIdx.x * blockDim.x + threadIdx.x;     // over 256*128
    int p = i >> 7, h = i & 127;
    // W1 rows p (Br) and 256+p (Bi); K = h (128)
    float br = B[i * 2 + 0], bi = B[i * 2 + 1];
    int pch = perm_k(h);
    float hb = __uint_as_float(f2tf32(br));
    g_W1Phi[p * H_DIM + pch] = hb;  g_W1Plo[p * H_DIM + pch] = br - hb;
    hb = __uint_as_float(f2tf32(bi));
    g_W1Phi[(P_DIM + p) * H_DIM + pch] = hb;  g_W1Plo[(P_DIM + p) * H_DIM + pch] = bi - hb;
    // W2 row h; K cols p (Cr) and 256+p (-Ci)
    float cr = C[(h * P_DIM + p) * 2 + 0];
    float ci = -C[(h * P_DIM + p) * 2 + 1];
    int pcp0 = perm_k(p), pcp1 = perm_k(256 + p);
    float hc = __uint_as_float(f2tf32(cr));
    g_W2Phi[h * NSEQ + pcp0] = hc;  g_W2Plo[h * NSEQ + pcp0] = cr - hc;
    hc = __uint_as_float(f2tf32(ci));
    g_W2Phi[h * NSEQ + pcp1] = hc;  g_W2Plo[h * NSEQ + pcp1] = ci - hc;
}

// ---------------------------------------------------------------------------
__device__ __forceinline__ void get_consts(const float* __restrict__ A_diag,
                                           const float* __restrict__ steps, int p,
                                           float& m11, float& m12, float& m21, float& m22,
                                           float& c1, float& c2) {
    float A  = fmaxf(A_diag[p], 0.0f);
    float dt = 1.0f / (1.0f + __expf(-steps[p]));
    float schur = 1.0f / (1.0f + dt * dt * A);
    m11 = 1.0f - dt * dt * A * schur;
    m12 = -dt * A * schur;
    m21 = dt * schur;
    m22 = schur;
    c1 = m11 * dt;
    c2 = m21 * dt;
}

// ---------------------------------------------------------------------------
// 3xTF32 NT GEMM, cp.async double-buffered, fragment loads via LDS128.
// BM=128, BN=64, BK=32, 256 threads (8 warps, 32x32 warp tiles).
// FUSE: scan-passA fused into epilogue (out = g_buall, N=512, BM rows = 1 chunk).
// EPI : residual add input*D (GEMM2).
#define A_STRIDE 36
#define STAGE_F  (128 * A_STRIDE + 128 * A_STRIDE)            // Ahi+Alo rows
#define OFF_ALO  (128 * A_STRIDE)
#define OFF_BHI  (2 * 128 * A_STRIDE)
#define OFF_BLO  (2 * 128 * A_STRIDE + 64 * A_STRIDE)
#define STAGE_TOT (2 * 128 * A_STRIDE + 2 * 64 * A_STRIDE)    // floats per stage = 13824

template <bool FUSE, bool EPI>
__global__ void __launch_bounds__(256)
gemm3x(const float* __restrict__ Ahi_g, const float* __restrict__ Alo_g,
       const float* __restrict__ Bhi_g, const float* __restrict__ Blo_g,
       float* __restrict__ out, int M, int N, int K,
       const float* __restrict__ resid, const float* __restrict__ Dv,
       const float* __restrict__ A_diag, const float* __restrict__ steps) {
    extern __shared__ float smem[];
    const int tid  = threadIdx.x;
    const int lane = tid & 31;
    const int wid  = tid >> 5;
    const int warp_m = (wid & 3) * 32;
    const int warp_n = (wid >> 2) * 32;
    const int gr = lane >> 2;
    const int kq = lane & 3;
    const int bm = blockIdx.y * 128, bn = blockIdx.x * 64;

    float acc[2][4][4];
    #pragma unroll
    for (int i = 0; i < 2; i++)
        #pragma unroll
        for (int j = 0; j < 4; j++)
            #pragma unroll
            for (int q = 0; q < 4; q++) acc[i][j][q] = 0.0f;

    const int nk = K >> 5;

    auto stage_load = [&](int kt, int s) {
        float* base = smem + s * STAGE_TOT;
        int k0 = kt << 5;
        #pragma unroll
        for (int it = 0; it < 4; it++) {
            int id = tid + it * 256;
            int r = id >> 3, c = (id & 7) << 2;
            const float* sh = Ahi_g + (size_t)(bm + r) * K + k0 + c;
            const float* sl = Alo_g + (size_t)(bm + r) * K + k0 + c;
            uint32_t dh = (uint32_t)__cvta_generic_to_shared(base + r * A_STRIDE + c);
            uint32_t dl = (uint32_t)__cvta_generic_to_shared(base + OFF_ALO + r * A_STRIDE + c);
            CP16(dh, sh); CP16(dl, sl);
        }
        #pragma unroll
        for (int it = 0; it < 2; it++) {
            int id = tid + it * 256;
            int r = id >> 3, c = (id & 7) << 2;
            const float* sh = Bhi_g + (size_t)(bn + r) * K + k0 + c;
            const float* sl = Blo_g + (size_t)(bn + r) * K + k0 + c;
            uint32_t dh = (uint32_t)__cvta_generic_to_shared(base + OFF_BHI + r * A_STRIDE + c);
            uint32_t dl = (uint32_t)__cvta_generic_to_shared(base + OFF_BLO + r * A_STRIDE + c);
            CP16(dh, sh); CP16(dl, sl);
        }
    };

    stage_load(0, 0);
    asm volatile("cp.async.commit_group;\n");

    for (int kt = 0; kt < nk; kt++) {
        int s = kt & 1;
        if (kt + 1 < nk) stage_load(kt + 1, s ^ 1);
        asm volatile("cp.async.commit_group;\n");
        asm volatile("cp.async.wait_group 1;\n");
        __syncthreads();

        float* base = smem + s * STAGE_TOT;
        #pragma unroll
        for (int h = 0; h < 2; h++) {
            // A fragments: per mt, rows r0 & r0+8, one float4 each (hi & lo)
            float4 ah[2][2], al[2][2];
            #pragma unroll
            for (int mt = 0; mt < 2; mt++) {
                int r0 = warp_m + mt * 16 + gr;
                ah[mt][0] = *reinterpret_cast<float4*>(base + r0 * A_STRIDE + kq * 8 + h * 4);
                ah[mt][1] = *reinterpret_cast<float4*>(base + (r0 + 8) * A_STRIDE + kq * 8 + h * 4);
                al[mt][0] = *reinterpret_cast<float4*>(base + OFF_ALO + r0 * A_STRIDE + kq * 8 + h * 4);
                al[mt][1] = *reinterpret_cast<float4*>(base + OFF_ALO + (r0 + 8) * A_STRIDE + kq * 8 + h * 4);
            }
            #pragma unroll
            for (int nt = 0; nt < 4; nt++) {
                int c0 = warp_n + nt * 8 + gr;
                float4 bh = *reinterpret_cast<float4*>(base + OFF_BHI + c0 * A_STRIDE + kq * 8 + h * 4);
                float4 bl = *reinterpret_cast<float4*>(base + OFF_BLO + c0 * A_STRIDE + kq * 8 + h * 4);
                #pragma unroll
                for (int mt = 0; mt < 2; mt++) {
                    float* d = acc[mt][nt];
                    // sub-k 0: components .x (k=kq), .y (k=kq+4)
                    uint32_t A0 = __float_as_uint(ah[mt][0].x), A1 = __float_as_uint(ah[mt][1].x);
                    uint32_t A2 = __float_as_uint(ah[mt][0].y), A3 = __float_as_uint(ah[mt][1].y);
                    uint32_t L0 = __float_as_uint(al[mt][0].x), L1 = __float_as_uint(al[mt][1].x);
                    uint32_t L2 = __float_as_uint(al[mt][0].y), L3 = __float_as_uint(al[mt][1].y);
                    uint32_t B0 = __float_as_uint(bh.x), B1 = __float_as_uint(bh.y);
                    uint32_t C0 = __float_as_uint(bl.x), C1 = __float_as_uint(bl.y);
                    mma_tf32(d, A0, A1, A2, A3, B0, B1);
                    mma_tf32(d, A0, A1, A2, A3, C0, C1);
                    mma_tf32(d, L0, L1, L2, L3, B0, B1);
                    // sub-k 1: components .z (k=kq+8), .w (k=kq+12)
                    A0 = __float_as_uint(ah[mt][0].z); A1 = __float_as_uint(ah[mt][1].z);
                    A2 = __float_as_uint(ah[mt][0].w); A3 = __float_as_uint(ah[mt][1].w);
                    L0 = __float_as_uint(al[mt][0].z); L1 = __float_as_uint(al[mt][1].z);
                    L2 = __float_as_uint(al[mt][0].w); L3 = __float_as_uint(al[mt][1].w);
                    B0 = __float_as_uint(bh.z); B1 = __float_as_uint(bh.w);
                    C0 = __float_as_uint(bl.z); C1 = __float_as_uint(bl.w);
                    mma_tf32(d, A0, A1, A2, A3, B0, B1);
                    mma_tf32(d, A0, A1, A2, A3, C0, C1);
                    mma_tf32(d, L0, L1, L2, L3, B0, B1);
                }
            }
        }
        __syncthreads();
    }

    // ---------------- Epilogue ----------------
    if (FUSE) {
        // write Bu to gmem and to smem (stride 65), then fused chunk scan
        float* sbu = smem;
        #pragma unroll
        for (int mt = 0; mt < 2; mt++)
            #pragma unroll
            for (int nt = 0; nt < 4; nt++) {
                int r0 = warp_m + mt * 16 + gr;
                int col = warp_n + nt * 8 + 2 * kq;
                float v00 = acc[mt][nt][0], v01 = acc[mt][nt][1];
                float v10 = acc[mt][nt][2], v11 = acc[mt][nt][3];
                *reinterpret_cast<float2*>(&out[(size_t)(bm + r0) * N + bn + col]) =
                    make_float2(v00, v01);
                *reinterpret_cast<float2*>(&out[(size_t)(bm + r0 + 8) * N + bn + col]) =
                    make_float2(v10, v11);
                sbu[r0 * 65 + col] = v00;       sbu[r0 * 65 + col + 1] = v01;
                sbu[(r0 + 8) * 65 + col] = v10; sbu[(r0 + 8) * 65 + col + 1] = v11;
            }
        __syncthreads();
        if (tid < 64) {
            int seq = bn + tid;
            int p = seq & (P_DIM - 1);
            float m11, m12, m21, m22, c1, c2;
            get_consts(A_diag, steps, p, m11, m12, m21, m22, c1, c2);
            float x1 = 0.0f, x2 = 0.0f;
            #pragma unroll 8
            for (int s = 0; s < CLEN; s++) {
                float u = sbu[s * 65 + tid];
                float n1 = fmaf(m11, x1, fmaf(m12, x2, c1 * u));
                float n2 = fmaf(m21, x1, fmaf(m22, x2, c2 * u));
                x1 = n1; x2 = n2;
            }
            g_final[blockIdx.y * NSEQ + seq] = make_float2(x1, x2);
        }
    } else {
        #pragma unroll
        for (int mt = 0; mt < 2; mt++)
            #pragma unroll
            for (int nt = 0; nt < 4; nt++) {
                int row = bm + warp_m + mt * 16 + gr;
                int col = bn + warp_n + nt * 8 + 2 * kq;
                float2 v0 = make_float2(acc[mt][nt][0], acc[mt][nt][1]);
                float2 v1 = make_float2(acc[mt][nt][2], acc[mt][nt][3]);
                if (EPI) {
                    float2 r0 = *reinterpret_cast<const float2*>(&resid[(size_t)row * N + col]);
                    float2 r1 = *reinterpret_cast<const float2*>(&resid[(size_t)(row + 8) * N + col]);
                    float d0 = Dv[col], d1 = Dv[col + 1];
                    v0.x += r0.x * d0; v0.y += r0.y * d1;
                    v1.x += r1.x * d0; v1.y += r1.y * d1;
                }
                *reinterpret_cast<float2*>(&out[(size_t)row * N + col]) = v0;
                *reinterpret_cast<float2*>(&out[(size_t)(row + 8) * N + col]) = v1;
            }
    }
}

// ---------------------------------------------------------------------------
// Pass B: per-seq Kogge-Stone scan over 128 chunk composites.
__global__ void scan_passB_par(const float* __restrict__ A_diag,
                               const float* __restrict__ steps) {
    int seq = blockIdx.x;
    int c   = threadIdx.x;
    int p   = seq & (P_DIM - 1);
    float m11, m12, m21, m22, c1u, c2u;
    get_consts(A_diag, steps, p, m11, m12, m21, m22, c1u, c2u);

    float a = m11, b = m12, cc = m21, d = m22;
    #pragma unroll
    for (int i = 0; i < 7; i++) {
        float na = a * a + b * cc;
        float nb = a * b + b * d;
        float nc = cc * a + d * cc;
        float nd = cc * b + d * d;
        a = na; b = nb; cc = nc; d = nd;
    }

    float2 f = g_final[c * NSEQ + seq];
    float ma = a, mb = b, mc = cc, md = d;
    float f1 = f.x, f2 = f.y;

    __shared__ float sa[NCHUNK], sb[NCHUNK], sc[NCHUNK], sd[NCHUNK];
    __shared__ float s1[NCHUNK], s2[NCHUNK];

    #pragma unroll
    for (int dstep = 1; dstep < NCHUNK; dstep <<= 1) {
        sa[c] = ma; sb[c] = mb; sc[c] = mc; sd[c] = md; s1[c] = f1; s2[c] = f2;
        __syncthreads();
        if (c >= dstep) {
            int j = c - dstep;
            float pa = sa[j], pb = sb[j], pc = sc[j], pd = sd[j];
            float p1 = s1[j], p2 = s2[j];
            float nf1 = ma * p1 + mb * p2 + f1;
            float nf2 = mc * p1 + md * p2 + f2;
            float na = ma * pa + mb * pc;
            float nb = ma * pb + mb * pd;
            float nc = mc * pa + md * pc;
            float nd = mc * pb + md * pd;
            ma = na; mb = nb; mc = nc; md = nd; f1 = nf1; f2 = nf2;
        }
        __syncthreads();
    }
    s1[c] = f1; s2[c] = f2;
    __syncthreads();
    float i1 = (c == 0) ? 0.0f : s1[c - 1];
    float i2 = (c == 0) ? 0.0f : s2[c - 1];
    g_initv[c * NSEQ + seq] = make_float2(i1, i2);
}

// Pass C: re-run chunk scan with correct init; emit x2 pre-split + K-permuted.
__global__ void scan_passC(const float* __restrict__ A_diag, const float* __restrict__ steps) {
    int t = threadIdx.x;
    int c = blockIdx.x;
    int p = t & (P_DIM - 1);
    float m11, m12, m21, m22, c1, c2;
    get_consts(A_diag, steps, p, m11, m12, m21, m22, c1, c2);

    int pc = perm_k(t);
    float2 s0 = g_initv[c * NSEQ + t];
    float x1 = s0.x, x2 = s0.y;
    const float* bu = g_buall + (size_t)c * CLEN * NSEQ + t;
    float* xh = g_x2Phi + (size_t)c * CLEN * NSEQ + pc;
    float* xl = g_x2Plo + (size_t)c * CLEN * NSEQ + pc;
    #pragma unroll 8
    for (int s = 0; s < CLEN; s++) {
        float u = bu[s * NSEQ];
        float n1 = fmaf(m11, x1, fmaf(m12, x2, c1 * u));
        float n2 = fmaf(m21, x1, fmaf(m22, x2, c2 * u));
        x1 = n1; x2 = n2;
        float hi = __uint_as_float(f2tf32(x2));
        xh[s * NSEQ] = hi;
        xl[s * NSEQ] = x2 - hi;
    }
}

// ---------------------------------------------------------------------------
extern "C" void kernel_launch(void* const* d_in, const int* in_sizes, int n_in,
                              void* d_out, int out_size) {
    const float* input  = (const float*)d_in[0];  // (L, H)
    const float* A_diag = (const float*)d_in[1];  // (P,)
    const float* B      = (const float*)d_in[2];  // (P, H, 2)
    const float* C      = (const float*)d_in[3];  // (H, P, 2)
    const float* D      = (const float*)d_in[4];  // (H,)
    const float* steps  = (const float*)d_in[5];  // (P,)
    float* out = (float*)d_out;                   // (L, H)

    float *p_bu, *p_inhi, *p_inlo, *p_w1hi, *p_w1lo, *p_w2hi, *p_w2lo, *p_x2hi, *p_x2lo;
    cudaGetSymbolAddress((void**)&p_bu,   g_buall);
    cudaGetSymbolAddress((void**)&p_inhi, g_inPhi);
    cudaGetSymbolAddress((void**)&p_inlo, g_inPlo);
    cudaGetSymbolAddress((void**)&p_w1hi, g_W1Phi);
    cudaGetSymbolAddress((void**)&p_w1lo, g_W1Plo);
    cudaGetSymbolAddress((void**)&p_w2hi, g_W2Phi);
    cudaGetSymbolAddress((void**)&p_w2lo, g_W2Plo);
    cudaGetSymbolAddress((void**)&p_x2hi, g_x2Phi);
    cudaGetSymbolAddress((void**)&p_x2lo, g_x2Plo);

    const int dyn = STAGE_TOT * 2 * sizeof(float);   // 110592 bytes
    cudaFuncSetAttribute(gemm3x<true, false>,
                         cudaFuncAttributeMaxDynamicSharedMemorySize, dyn);
    cudaFuncSetAttribute(gemm3x<false, true>,
                         cudaFuncAttributeMaxDynamicSharedMemorySize, dyn);

    prep_input<<<L_SEQ * H_DIM / 1024, 1024>>>(input);
    prep_w<<<P_DIM * H_DIM / 256, 256>>>(B, C);

    // GEMM1 + fused passA: Bu = input @ W1^T  (16384 x 512, K=128)
    gemm3x<true, false><<<dim3(NSEQ / 64, L_SEQ / 128), 256, dyn>>>(
        p_inhi, p_inlo, p_w1hi, p_w1lo, p_bu, L_SEQ, NSEQ, H_DIM,
        nullptr, nullptr, A_diag, steps);

    scan_passB_par<<<NSEQ, NCHUNK>>>(A_diag, steps);
    scan_passC<<<NCHUNK, NSEQ>>>(A_diag, steps);

    // GEMM2: ys = x2 @ W2^T + input * D  (16384 x 128, K=512)
    gemm3x<false, true><<<dim3(H_DIM / 64, L_SEQ / 128), 256, dyn>>>(
        p_x2hi, p_x2lo, p_w2hi, p_w2lo, out, L_SEQ, H_DIM, NSEQ,
        input, D, nullptr, nullptr);
}

// round 4
// speedup vs baseline: 1.2837x; 1.2837x over previous
#include <cuda_runtime.h>
#include <math.h>
#include <stdint.h>

#define L_SEQ 16384
#define H_DIM 128
#define P_DIM 256
#define NSEQ  512          // 256 channels x {re, im}
#define NCHUNK 128
#define CLEN   128         // NCHUNK * CLEN == L_SEQ

// ---------------------------------------------------------------------------
// Scratch (device globals; no allocations allowed)
__device__ float  g_buall[L_SEQ * NSEQ];    // (L, 512) fp32 Bu (for scan passC)
__device__ float  g_x2P[L_SEQ * NSEQ];      // x2 fp32, K-permuted (GEMM2 A)
__device__ float  g_inP[L_SEQ * H_DIM];     // input fp32, K-permuted (GEMM1 A)
__device__ float  g_W1P[NSEQ * H_DIM];      // [Br;Bi] fp32, K-permuted (GEMM1 B)
__device__ float  g_W2P[H_DIM * NSEQ];      // [Cr,-Ci] fp32, K-permuted (GEMM2 B)
__device__ float2 g_final[NCHUNK * NSEQ];
__device__ float2 g_initv[NCHUNK * NSEQ];

// ---------------------------------------------------------------------------
__device__ __forceinline__ uint32_t f2tf32(float v) {
    uint32_t r;
    asm("cvt.rna.tf32.f32 %0, %1;" : "=r"(r) : "f"(v));
    return r;
}
__device__ __forceinline__ int perm_k(int k) {  // within 32-k blocks: k -> (k%4)*8 + (k%32)/4
    return (k & ~31) | (((k & 3) << 3) | ((k & 31) >> 2));
}
__device__ __forceinline__ float4 hi4(float4 v) {
    float4 h;
    h.x = __uint_as_float(f2tf32(v.x));
    h.y = __uint_as_float(f2tf32(v.y));
    h.z = __uint_as_float(f2tf32(v.z));
    h.w = __uint_as_float(f2tf32(v.w));
    return h;
}
__device__ __forceinline__ float4 lo4(float4 v, float4 h) {
    return make_float4(v.x - h.x, v.y - h.y, v.z - h.z, v.w - h.w);
}
__device__ __forceinline__ void mma_tf32(float* d, float a0, float a1,
                                         float a2, float a3, float b0, float b1) {
    asm volatile(
        "mma.sync.aligned.m16n8k8.row.col.f32.tf32.tf32.f32 "
        "{%0,%1,%2,%3},{%4,%5,%6,%7},{%8,%9},{%0,%1,%2,%3};\n"
        : "+f"(d[0]), "+f"(d[1]), "+f"(d[2]), "+f"(d[3])
        : "r"(__float_as_uint(a0)), "r"(__float_as_uint(a1)),
          "r"(__float_as_uint(a2)), "r"(__float_as_uint(a3)),
          "r"(__float_as_uint(b0)), "r"(__float_as_uint(b1)));
}
#define CP16(dst_u32, src_ptr) \
    asm volatile("cp.async.cg.shared.global [%0], [%1], 16;\n" :: "r"(dst_u32), "l"(src_ptr))

// ---------------------------------------------------------------------------
// Prep: permute K layout (fp32, no split)
__global__ void prep_input(const float* __restrict__ in) {
    int idx = blockIdx.x * blockDim.x + threadIdx.x;   // over L*H
    float v = in[idx];
    int row = idx >> 7, col = idx & 127;
    g_inP[(row << 7) | perm_k(col)] = v;
}

__global__ void prep_w(const float* __restrict__ B, const float* __restrict__ C) {
    int i = blockIdx.x * blockDim.x + threadIdx.x;     // over 256*128
    int p = i >> 7, h = i & 127;
    float br = B[i * 2 + 0], bi = B[i * 2 + 1];
    int pch = perm_k(h);
    g_W1P[p * H_DIM + pch]           = br;
    g_W1P[(P_DIM + p) * H_DIM + pch] = bi;
    float cr = C[(h * P_DIM + p) * 2 + 0];
    float ci = -C[(h * P_DIM + p) * 2 + 1];
    g_W2P[h * NSEQ + perm_k(p)]       = cr;
    g_W2P[h * NSEQ + perm_k(256 + p)] = ci;
}

// ---------------------------------------------------------------------------
__device__ __forceinline__ void get_consts(const float* __restrict__ A_diag,
                                           const float* __restrict__ steps, int p,
                                           float& m11, float& m12, float& m21, float& m22,
                                           float& c1, float& c2) {
    float A  = fmaxf(A_diag[p], 0.0f);
    float dt = 1.0f / (1.0f + __expf(-steps[p]));
    float schur = 1.0f / (1.0f + dt * dt * A);
    m11 = 1.0f - dt * dt * A * schur;
    m12 = -dt * A * schur;
    m21 = dt * schur;
    m22 = schur;
    c1 = m11 * dt;
    c2 = m21 * dt;
}

// ---------------------------------------------------------------------------
// 3xTF32 NT GEMM: fp32 smem tiles, register hi/lo split, LDS128 fragments.
// BM=128, BN=64, BK=32, 256 threads (8 warps, 32x32 warp tiles), cp.async x2.
// FUSE: scan-passA fused into epilogue (out = g_buall, BM rows = 1 chunk).
#define STRD  36
#define OFF_B (128 * STRD)
#define STAGE_TOT ((128 + 64) * STRD)      // 6912 floats per stage

template <bool FUSE, bool EPI>
__global__ void __launch_bounds__(256)
gemm3x(const float* __restrict__ A_g, const float* __restrict__ B_g,
       float* __restrict__ out, int M, int N, int K,
       const float* __restrict__ resid, const float* __restrict__ Dv,
       const float* __restrict__ A_diag, const float* __restrict__ steps) {
    extern __shared__ float smem[];
    const int tid  = threadIdx.x;
    const int lane = tid & 31;
    const int wid  = tid >> 5;
    const int warp_m = (wid & 3) * 32;
    const int warp_n = (wid >> 2) * 32;
    const int gr = lane >> 2;
    const int kq = lane & 3;
    const int bm = blockIdx.y * 128, bn = blockIdx.x * 64;

    float acc[2][4][4];
    #pragma unroll
    for (int i = 0; i < 2; i++)
        #pragma unroll
        for (int j = 0; j < 4; j++)
            #pragma unroll
            for (int q = 0; q < 4; q++) acc[i][j][q] = 0.0f;

    const int nk = K >> 5;

    auto stage_load = [&](int kt, int s) {
        float* base = smem + s * STAGE_TOT;
        int k0 = kt << 5;
        #pragma unroll
        for (int it = 0; it < 4; it++) {
            int id = tid + it * 256;
            int r = id >> 3, c = (id & 7) << 2;
            const float* src = A_g + (size_t)(bm + r) * K + k0 + c;
            uint32_t dst = (uint32_t)__cvta_generic_to_shared(base + r * STRD + c);
            CP16(dst, src);
        }
        #pragma unroll
        for (int it = 0; it < 2; it++) {
            int id = tid + it * 256;
            int r = id >> 3, c = (id & 7) << 2;
            const float* src = B_g + (size_t)(bn + r) * K + k0 + c;
            uint32_t dst = (uint32_t)__cvta_generic_to_shared(base + OFF_B + r * STRD + c);
            CP16(dst, src);
        }
    };

    stage_load(0, 0);
    asm volatile("cp.async.commit_group;\n");

    for (int kt = 0; kt < nk; kt++) {
        int s = kt & 1;
        if (kt + 1 < nk) stage_load(kt + 1, s ^ 1);
        asm volatile("cp.async.commit_group;\n");
        asm volatile("cp.async.wait_group 1;\n");
        __syncthreads();

        float* base = smem + s * STAGE_TOT;
        #pragma unroll
        for (int h = 0; h < 2; h++) {
            // A fragments: per mt, rows r0 & r0+8; split in registers.
            float4 ah[2][2], al[2][2];
            #pragma unroll
            for (int mt = 0; mt < 2; mt++) {
                int r0 = warp_m + mt * 16 + gr;
                float4 w0 = *reinterpret_cast<float4*>(base + r0 * STRD + kq * 8 + h * 4);
                float4 w1 = *reinterpret_cast<float4*>(base + (r0 + 8) * STRD + kq * 8 + h * 4);
                ah[mt][0] = hi4(w0); al[mt][0] = lo4(w0, ah[mt][0]);
                ah[mt][1] = hi4(w1); al[mt][1] = lo4(w1, ah[mt][1]);
            }
            #pragma unroll
            for (int nt = 0; nt < 4; nt++) {
                int c0 = warp_n + nt * 8 + gr;
                float4 bw = *reinterpret_cast<float4*>(base + OFF_B + c0 * STRD + kq * 8 + h * 4);
                float4 bh = hi4(bw);
                float4 bl = lo4(bw, bh);
                #pragma unroll
                for (int mt = 0; mt < 2; mt++) {
                    float* d = acc[mt][nt];
                    // sub-k 0: components .x (k=kq), .y (k=kq+4)
                    mma_tf32(d, ah[mt][0].x, ah[mt][1].x, ah[mt][0].y, ah[mt][1].y, bh.x, bh.y);
                    mma_tf32(d, ah[mt][0].x, ah[mt][1].x, ah[mt][0].y, ah[mt][1].y, bl.x, bl.y);
                    mma_tf32(d, al[mt][0].x, al[mt][1].x, al[mt][0].y, al[mt][1].y, bh.x, bh.y);
                    // sub-k 1: components .z (k=kq+8), .w (k=kq+12)
                    mma_tf32(d, ah[mt][0].z, ah[mt][1].z, ah[mt][0].w, ah[mt][1].w, bh.z, bh.w);
                    mma_tf32(d, ah[mt][0].z, ah[mt][1].z, ah[mt][0].w, ah[mt][1].w, bl.z, bl.w);
                    mma_tf32(d, al[mt][0].z, al[mt][1].z, al[mt][0].w, al[mt][1].w, bh.z, bh.w);
                }
            }
        }
        __syncthreads();
    }

    // ---------------- Epilogue ----------------
    if (FUSE) {
        // write Bu to gmem and to smem (stride 65), then fused chunk scan (passA)
        float* sbu = smem;
        #pragma unroll
        for (int mt = 0; mt < 2; mt++)
            #pragma unroll
            for (int nt = 0; nt < 4; nt++) {
                int r0 = warp_m + mt * 16 + gr;
                int col = warp_n + nt * 8 + 2 * kq;
                float v00 = acc[mt][nt][0], v01 = acc[mt][nt][1];
                float v10 = acc[mt][nt][2], v11 = acc[mt][nt][3];
                *reinterpret_cast<float2*>(&out[(size_t)(bm + r0) * N + bn + col]) =
                    make_float2(v00, v01);
                *reinterpret_cast<float2*>(&out[(size_t)(bm + r0 + 8) * N + bn + col]) =
                    make_float2(v10, v11);
                sbu[r0 * 65 + col] = v00;       sbu[r0 * 65 + col + 1] = v01;
                sbu[(r0 + 8) * 65 + col] = v10; sbu[(r0 + 8) * 65 + col + 1] = v11;
            }
        __syncthreads();
        if (tid < 64) {
            int seq = bn + tid;
            int p = seq & (P_DIM - 1);
            float m11, m12, m21, m22, c1, c2;
            get_consts(A_diag, steps, p, m11, m12, m21, m22, c1, c2);
            float x1 = 0.0f, x2 = 0.0f;
            #pragma unroll 8
            for (int s = 0; s < CLEN; s++) {
                float u = sbu[s * 65 + tid];
                float n1 = fmaf(m11, x1, fmaf(m12, x2, c1 * u));
                float n2 = fmaf(m21, x1, fmaf(m22, x2, c2 * u));
                x1 = n1; x2 = n2;
            }
            g_final[blockIdx.y * NSEQ + seq] = make_float2(x1, x2);
        }
    } else {
        #pragma unroll
        for (int mt = 0; mt < 2; mt++)
            #pragma unroll
            for (int nt = 0; nt < 4; nt++) {
                int row = bm + warp_m + mt * 16 + gr;
                int col = bn + warp_n + nt * 8 + 2 * kq;
                float2 v0 = make_float2(acc[mt][nt][0], acc[mt][nt][1]);
                float2 v1 = make_float2(acc[mt][nt][2], acc[mt][nt][3]);
                if (EPI) {
                    float2 r0 = *reinterpret_cast<const float2*>(&resid[(size_t)row * N + col]);
                    float2 r1 = *reinterpret_cast<const float2*>(&resid[(size_t)(row + 8) * N + col]);
                    float d0 = Dv[col], d1 = Dv[col + 1];
                    v0.x += r0.x * d0; v0.y += r0.y * d1;
                    v1.x += r1.x * d0; v1.y += r1.y * d1;
                }
                *reinterpret_cast<float2*>(&out[(size_t)row * N + col]) = v0;
                *reinterpret_cast<float2*>(&out[(size_t)(row + 8) * N + col]) = v1;
            }
    }
}

// ---------------------------------------------------------------------------
// Pass B: per-seq Kogge-Stone scan over 128 chunk composites.
__global__ void scan_passB_par(const float* __restrict__ A_diag,
                               const float* __restrict__ steps) {
    int seq = blockIdx.x;
    int c   = threadIdx.x;
    int p   = seq & (P_DIM - 1);
    float m11, m12, m21, m22, c1u, c2u;
    get_consts(A_diag, steps, p, m11, m12, m21, m22, c1u, c2u);

    float a = m11, b = m12, cc = m21, d = m22;
    #pragma unroll
    for (int i = 0; i < 7; i++) {   // M^128
        float na = a * a + b * cc;
        float nb = a * b + b * d;
        float nc = cc * a + d * cc;
        float nd = cc * b + d * d;
        a = na; b = nb; cc = nc; d = nd;
    }

    float2 f = g_final[c * NSEQ + seq];
    float ma = a, mb = b, mc = cc, md = d;
    float f1 = f.x, f2 = f.y;

    __shared__ float sa[NCHUNK], sb[NCHUNK], sc[NCHUNK], sd[NCHUNK];
    __shared__ float s1[NCHUNK], s2[NCHUNK];

    #pragma unroll
    for (int dstep = 1; dstep < NCHUNK; dstep <<= 1) {
        sa[c] = ma; sb[c] = mb; sc[c] = mc; sd[c] = md; s1[c] = f1; s2[c] = f2;
        __syncthreads();
        if (c >= dstep) {
            int j = c - dstep;
            float pa = sa[j], pb = sb[j], pc = sc[j], pd = sd[j];
            float p1 = s1[j], p2 = s2[j];
            float nf1 = ma * p1 + mb * p2 + f1;
            float nf2 = mc * p1 + md * p2 + f2;
            float na = ma * pa + mb * pc;
            float nb = ma * pb + mb * pd;
            float nc = mc * pa + md * pc;
            float nd = mc * pb + md * pd;
            ma = na; mb = nb; mc = nc; md = nd; f1 = nf1; f2 = nf2;
        }
        __syncthreads();
    }
    s1[c] = f1; s2[c] = f2;
    __syncthreads();
    float i1 = (c == 0) ? 0.0f : s1[c - 1];
    float i2 = (c == 0) ? 0.0f : s2[c - 1];
    g_initv[c * NSEQ + seq] = make_float2(i1, i2);
}

// Pass C: re-run chunk scan with correct init; emit x2 fp32, K-permuted.
__global__ void scan_passC(const float* __restrict__ A_diag, const float* __restrict__ steps) {
    int t = threadIdx.x;
    int c = blockIdx.x;
    int p = t & (P_DIM - 1);
    float m11, m12, m21, m22, c1, c2;
    get_consts(A_diag, steps, p, m11, m12, m21, m22, c1, c2);

    int pc = perm_k(t);
    float2 s0 = g_initv[c * NSEQ + t];
    float x1 = s0.x, x2 = s0.y;
    const float* bu = g_buall + (size_t)c * CLEN * NSEQ + t;
    float*       xo = g_x2P   + (size_t)c * CLEN * NSEQ + pc;
    #pragma unroll 8
    for (int s = 0; s < CLEN; s++) {
        float u = bu[s * NSEQ];
        float n1 = fmaf(m11, x1, fmaf(m12, x2, c1 * u));
        float n2 = fmaf(m21, x1, fmaf(m22, x2, c2 * u));
        x1 = n1; x2 = n2;
        xo[s * NSEQ] = x2;
    }
}

// ---------------------------------------------------------------------------
extern "C" void kernel_launch(void* const* d_in, const int* in_sizes, int n_in,
                              void* d_out, int out_size) {
    const float* input  = (const float*)d_in[0];  // (L, H)
    const float* A_diag = (const float*)d_in[1];  // (P,)
    const float* B      = (const float*)d_in[2];  // (P, H, 2)
    const float* C      = (const float*)d_in[3];  // (H, P, 2)
    const float* D      = (const float*)d_in[4];  // (H,)
    const float* steps  = (const float*)d_in[5];  // (P,)
    float* out = (float*)d_out;                   // (L, H)

    float *p_bu, *p_in, *p_w1, *p_w2, *p_x2;
    cudaGetSymbolAddress((void**)&p_bu, g_buall);
    cudaGetSymbolAddress((void**)&p_in, g_inP);
    cudaGetSymbolAddress((void**)&p_w1, g_W1P);
    cudaGetSymbolAddress((void**)&p_w2, g_W2P);
    cudaGetSymbolAddress((void**)&p_x2, g_x2P);

    const int dyn = STAGE_TOT * 2 * sizeof(float);   // 55296 bytes
    cudaFuncSetAttribute(gemm3x<true, false>,
                         cudaFuncAttributeMaxDynamicSharedMemorySize, dyn);
    cudaFuncSetAttribute(gemm3x<false, true>,
                         cudaFuncAttributeMaxDynamicSharedMemorySize, dyn);

    prep_input<<<L_SEQ * H_DIM / 1024, 1024>>>(input);
    prep_w<<<P_DIM * H_DIM / 256, 256>>>(B, C);

    // GEMM1 + fused passA: Bu = input @ W1^T  (16384 x 512, K=128)
    gemm3x<true, false><<<dim3(NSEQ / 64, L_SEQ / 128), 256, dyn>>>(
        p_in, p_w1, p_bu, L_SEQ, NSEQ, H_DIM, nullptr, nullptr, A_diag, steps);

    scan_passB_par<<<NSEQ, NCHUNK>>>(A_diag, steps);
    scan_passC<<<NCHUNK, NSEQ>>>(A_diag, steps);

    // GEMM2: ys = x2 @ W2^T + input * D  (16384 x 128, K=512)
    gemm3x<false, true><<<dim3(H_DIM / 64, L_SEQ / 128), 256, dyn>>>(
        p_x2, p_w2, out, L_SEQ, H_DIM, NSEQ, input, D, nullptr, nullptr);
}

// round 5
// speedup vs baseline: 1.5423x; 1.2015x over previous
#include <cuda_runtime.h>
#include <cuda_bf16.h>
#include <math.h>
#include <stdint.h>

#define L_SEQ 16384
#define H_DIM 128
#define P_DIM 256
#define NSEQ  512          // 256 channels x {re, im}
#define NCHUNK 128
#define CLEN   128

// ---------------------------------------------------------------------------
// Scratch (device globals)
__device__ float    g_buall[L_SEQ * NSEQ];        // fp32 Bu (for passC)
__device__ uint32_t g_inH[L_SEQ * (H_DIM / 2)];   // input hi bf16-pairs, permuted
__device__ uint32_t g_inL[L_SEQ * (H_DIM / 2)];
__device__ uint32_t g_W1H[NSEQ * (H_DIM / 2)];    // [Br;Bi]
__device__ uint32_t g_W1L[NSEQ * (H_DIM / 2)];
__device__ uint32_t g_W2H[H_DIM * (NSEQ / 2)];    // [Cr,-Ci]
__device__ uint32_t g_W2L[H_DIM * (NSEQ / 2)];
__device__ uint32_t g_x2H[L_SEQ * (NSEQ / 2)];    // x2 split, permuted
__device__ uint32_t g_x2L[L_SEQ * (NSEQ / 2)];
__device__ float2   g_final[NCHUNK * NSEQ];
__device__ float2   g_initv[NCHUNK * NSEQ];

// ---------------------------------------------------------------------------
__device__ __forceinline__ uint32_t packbf(float lo, float hi) {  // lo -> bits[15:0]
    uint32_t r;
    asm("cvt.rn.bf16x2.f32 %0, %1, %2;" : "=r"(r) : "f"(hi), "f"(lo));
    return r;
}
__device__ __forceinline__ int pair_pos(int P) {  // permute pairs within 16-pair groups
    int pi = P & 15;
    return (P & ~15) | (((pi & 3) << 2) | (pi >> 2));
}
// split v into bf16 hi (returned as float) ; caller computes lo = v - hi
__device__ __forceinline__ float bfhi(float v) {
    return __bfloat162float(__float2bfloat16_rn(v));
}
__device__ __forceinline__ void mma_bf16(float* d, uint32_t a0, uint32_t a1,
                                         uint32_t a2, uint32_t a3,
                                         uint32_t b0, uint32_t b1) {
    asm volatile(
        "mma.sync.aligned.m16n8k16.row.col.f32.bf16.bf16.f32 "
        "{%0,%1,%2,%3},{%4,%5,%6,%7},{%8,%9},{%0,%1,%2,%3};\n"
        : "+f"(d[0]), "+f"(d[1]), "+f"(d[2]), "+f"(d[3])
        : "r"(a0), "r"(a1), "r"(a2), "r"(a3), "r"(b0), "r"(b1));
}
#define CP16(dst_u32, src_ptr) \
    asm volatile("cp.async.cg.shared.global [%0], [%1], 16;\n" :: "r"(dst_u32), "l"(src_ptr))

// ---------------------------------------------------------------------------
// Prep: split input (L x 128) into bf16 hi/lo pair arrays, pair-permuted.
__global__ void prep_input(const float* __restrict__ in) {
    int i = blockIdx.x * blockDim.x + threadIdx.x;   // over L * 64 pairs
    int row = i >> 6, P = i & 63;
    float v0 = in[row * 128 + 2 * P];
    float v1 = in[row * 128 + 2 * P + 1];
    float h0 = bfhi(v0), h1 = bfhi(v1);
    int col = pair_pos(P);
    g_inH[row * 64 + col] = packbf(h0, h1);
    g_inL[row * 64 + col] = packbf(v0 - h0, v1 - h1);
}

// Prep weights: W1 (512 x 128) and W2 (128 x 512), split + permuted.
__global__ void prep_w(const float* __restrict__ B, const float* __restrict__ C) {
    int i = blockIdx.x * blockDim.x + threadIdx.x;   // 32768 threads

    {   // W1 pair: rows 0..511, 64 pairs
        int row = i >> 6, P = i & 63;
        float v0, v1;
        if (row < P_DIM) {
            v0 = B[(row * H_DIM + 2 * P) * 2 + 0];
            v1 = B[(row * H_DIM + 2 * P + 1) * 2 + 0];
        } else {
            int r = row - P_DIM;
            v0 = B[(r * H_DIM + 2 * P) * 2 + 1];
            v1 = B[(r * H_DIM + 2 * P + 1) * 2 + 1];
        }
        float h0 = bfhi(v0), h1 = bfhi(v1);
        int col = pair_pos(P);
        g_W1H[row * 64 + col] = packbf(h0, h1);
        g_W1L[row * 64 + col] = packbf(v0 - h0, v1 - h1);
    }
    {   // W2 pair: rows 0..127, 256 pairs (K=512)
        int row = i >> 8, P = i & 255;
        int k0 = 2 * P;
        float v0, v1;
        if (k0 < P_DIM) {
            v0 =  C[(row * P_DIM + k0) * 2 + 0];
            v1 =  C[(row * P_DIM + k0 + 1) * 2 + 0];
        } else {
            v0 = -C[(row * P_DIM + k0 - P_DIM) * 2 + 1];
            v1 = -C[(row * P_DIM + k0 + 1 - P_DIM) * 2 + 1];
        }
        float h0 = bfhi(v0), h1 = bfhi(v1);
        int col = pair_pos(P);
        g_W2H[row * 256 + col] = packbf(h0, h1);
        g_W2L[row * 256 + col] = packbf(v0 - h0, v1 - h1);
    }
}

// ---------------------------------------------------------------------------
__device__ __forceinline__ void get_consts(const float* __restrict__ A_diag,
                                           const float* __restrict__ steps, int p,
                                           float& m11, float& m12, float& m21, float& m22,
                                           float& c1, float& c2) {
    float A  = fmaxf(A_diag[p], 0.0f);
    float dt = 1.0f / (1.0f + __expf(-steps[p]));
    float schur = 1.0f / (1.0f + dt * dt * A);
    m11 = 1.0f - dt * dt * A * schur;
    m12 = -dt * A * schur;
    m21 = dt * schur;
    m22 = schur;
    c1 = m11 * dt;
    c2 = m21 * dt;
}

// ---------------------------------------------------------------------------
// 3xBF16 NT GEMM. Tiles in smem as bf16 pairs (u32), pair-permuted for LDS128.
// BM=128, BN=64, BK=32, 256 threads (8 warps, 32x32 warp tiles), cp.async x2.
// smem per stage (u32): AH 2048 | AL 2048 | BH 1024 | BL 1024 = 6144 (24KB)
#define OFF_AL 2048
#define OFF_BH 4096
#define OFF_BL 5120
#define STAGE_U 6144

template <bool FUSE, bool EPI>
__global__ void __launch_bounds__(256)
gemm_bf16x3(const uint32_t* __restrict__ AH_g, const uint32_t* __restrict__ AL_g,
            const uint32_t* __restrict__ BH_g, const uint32_t* __restrict__ BL_g,
            float* __restrict__ out, int M, int N, int K,
            const float* __restrict__ resid, const float* __restrict__ Dv,
            const float* __restrict__ A_diag, const float* __restrict__ steps) {
    extern __shared__ uint32_t smem_u[];
    const int tid  = threadIdx.x;
    const int lane = tid & 31;
    const int wid  = tid >> 5;
    const int warp_m = (wid & 3) * 32;
    const int warp_n = (wid >> 2) * 32;
    const int gr = lane >> 2;
    const int kq = lane & 3;
    const int bm = blockIdx.y * 128, bn = blockIdx.x * 64;
    const int KW = K >> 1;           // gmem row length in u32 pairs

    float acc[2][4][4];
    #pragma unroll
    for (int i = 0; i < 2; i++)
        #pragma unroll
        for (int j = 0; j < 4; j++)
            #pragma unroll
            for (int q = 0; q < 4; q++) acc[i][j][q] = 0.0f;

    const int nk = K >> 5;

    auto stage_load = [&](int kt, int s) {
        uint32_t* base = smem_u + s * STAGE_U;
        int kofs = kt << 4;                       // 16 u32 per k-tile row
        #pragma unroll
        for (int it = 0; it < 2; it++) {          // A hi + lo: 512 chunks each
            int id = tid + it * 256;
            int r = id >> 2, c4 = (id & 3) << 2;
            const uint32_t* sh = AH_g + (size_t)(bm + r) * KW + kofs + c4;
            const uint32_t* sl = AL_g + (size_t)(bm + r) * KW + kofs + c4;
            CP16((uint32_t)__cvta_generic_to_shared(base + r * 16 + c4), sh);
            CP16((uint32_t)__cvta_generic_to_shared(base + OFF_AL + r * 16 + c4), sl);
        }
        {                                          // B hi + lo: 256 chunks each
            int r = tid >> 2, c4 = (tid & 3) << 2;
            const uint32_t* sh = BH_g + (size_t)(bn + r) * KW + kofs + c4;
            const uint32_t* sl = BL_g + (size_t)(bn + r) * KW + kofs + c4;
            CP16((uint32_t)__cvta_generic_to_shared(base + OFF_BH + r * 16 + c4), sh);
            CP16((uint32_t)__cvta_generic_to_shared(base + OFF_BL + r * 16 + c4), sl);
        }
    };

    stage_load(0, 0);
    asm volatile("cp.async.commit_group;\n");

    for (int kt = 0; kt < nk; kt++) {
        int s = kt & 1;
        if (kt + 1 < nk) stage_load(kt + 1, s ^ 1);
        asm volatile("cp.async.commit_group;\n");
        asm volatile("cp.async.wait_group 1;\n");
        __syncthreads();

        uint32_t* base = smem_u + s * STAGE_U;
        // A fragments: one LDS128 per row covers both k16 sub-blocks.
        uint4 AH[2][2], AL[2][2];
        #pragma unroll
        for (int mt = 0; mt < 2; mt++) {
            int r0 = warp_m + mt * 16 + gr;
            AH[mt][0] = *reinterpret_cast<uint4*>(base + r0 * 16 + kq * 4);
            AH[mt][1] = *reinterpret_cast<uint4*>(base + (r0 + 8) * 16 + kq * 4);
            AL[mt][0] = *reinterpret_cast<uint4*>(base + OFF_AL + r0 * 16 + kq * 4);
            AL[mt][1] = *reinterpret_cast<uint4*>(base + OFF_AL + (r0 + 8) * 16 + kq * 4);
        }
        #pragma unroll
        for (int nt = 0; nt < 4; nt++) {
            int c0 = warp_n + nt * 8 + gr;
            uint4 BH = *reinterpret_cast<uint4*>(base + OFF_BH + c0 * 16 + kq * 4);
            uint4 BL = *reinterpret_cast<uint4*>(base + OFF_BL + c0 * 16 + kq * 4);
            #pragma unroll
            for (int mt = 0; mt < 2; mt++) {
                float* d = acc[mt][nt];
                // k16 block 0: pairs .x (k=2kq), .y (k=2kq+8)
                mma_bf16(d, AH[mt][0].x, AH[mt][1].x, AH[mt][0].y, AH[mt][1].y, BH.x, BH.y);
                mma_bf16(d, AH[mt][0].x, AH[mt][1].x, AH[mt][0].y, AH[mt][1].y, BL.x, BL.y);
                mma_bf16(d, AL[mt][0].x, AL[mt][1].x, AL[mt][0].y, AL[mt][1].y, BH.x, BH.y);
                // k16 block 1: pairs .z (k=16+2kq), .w (k=24+2kq)
                mma_bf16(d, AH[mt][0].z, AH[mt][1].z, AH[mt][0].w, AH[mt][1].w, BH.z, BH.w);
                mma_bf16(d, AH[mt][0].z, AH[mt][1].z, AH[mt][0].w, AH[mt][1].w, BL.z, BL.w);
                mma_bf16(d, AL[mt][0].z, AL[mt][1].z, AL[mt][0].w, AL[mt][1].w, BH.z, BH.w);
            }
        }
        __syncthreads();
    }

    // ---------------- Epilogue ----------------
    if (FUSE) {
        float* sbu = reinterpret_cast<float*>(smem_u);
        #pragma unroll
        for (int mt = 0; mt < 2; mt++)
            #pragma unroll
            for (int nt = 0; nt < 4; nt++) {
                int r0 = warp_m + mt * 16 + gr;
                int col = warp_n + nt * 8 + 2 * kq;
                float v00 = acc[mt][nt][0], v01 = acc[mt][nt][1];
                float v10 = acc[mt][nt][2], v11 = acc[mt][nt][3];
                *reinterpret_cast<float2*>(&out[(size_t)(bm + r0) * N + bn + col]) =
                    make_float2(v00, v01);
                *reinterpret_cast<float2*>(&out[(size_t)(bm + r0 + 8) * N + bn + col]) =
                    make_float2(v10, v11);
                sbu[r0 * 65 + col] = v00;       sbu[r0 * 65 + col + 1] = v01;
                sbu[(r0 + 8) * 65 + col] = v10; sbu[(r0 + 8) * 65 + col + 1] = v11;
            }
        __syncthreads();
        if (tid < 64) {
            int seq = bn + tid;
            int p = seq & (P_DIM - 1);
            float m11, m12, m21, m22, c1, c2;
            get_consts(A_diag, steps, p, m11, m12, m21, m22, c1, c2);
            float x1 = 0.0f, x2 = 0.0f;
            #pragma unroll 8
            for (int s = 0; s < CLEN; s++) {
                float u = sbu[s * 65 + tid];
                float n1 = fmaf(m11, x1, fmaf(m12, x2, c1 * u));
                float n2 = fmaf(m21, x1, fmaf(m22, x2, c2 * u));
                x1 = n1; x2 = n2;
            }
            g_final[blockIdx.y * NSEQ + seq] = make_float2(x1, x2);
        }
    } else {
        #pragma unroll
        for (int mt = 0; mt < 2; mt++)
            #pragma unroll
            for (int nt = 0; nt < 4; nt++) {
                int row = bm + warp_m + mt * 16 + gr;
                int col = bn + warp_n + nt * 8 + 2 * kq;
                float2 v0 = make_float2(acc[mt][nt][0], acc[mt][nt][1]);
                float2 v1 = make_float2(acc[mt][nt][2], acc[mt][nt][3]);
                if (EPI) {
                    float2 r0 = *reinterpret_cast<const float2*>(&resid[(size_t)row * N + col]);
                    float2 r1 = *reinterpret_cast<const float2*>(&resid[(size_t)(row + 8) * N + col]);
                    float d0 = Dv[col], d1 = Dv[col + 1];
                    v0.x += r0.x * d0; v0.y += r0.y * d1;
                    v1.x += r1.x * d0; v1.y += r1.y * d1;
                }
                *reinterpret_cast<float2*>(&out[(size_t)row * N + col]) = v0;
                *reinterpret_cast<float2*>(&out[(size_t)(row + 8) * N + col]) = v1;
            }
    }
}

// ---------------------------------------------------------------------------
// Pass B: per-seq Kogge-Stone scan over 128 chunk composites.
__global__ void scan_passB_par(const float* __restrict__ A_diag,
                               const float* __restrict__ steps) {
    int seq = blockIdx.x;
    int c   = threadIdx.x;
    int p   = seq & (P_DIM - 1);
    float m11, m12, m21, m22, c1u, c2u;
    get_consts(A_diag, steps, p, m11, m12, m21, m22, c1u, c2u);

    float a = m11, b = m12, cc = m21, d = m22;
    #pragma unroll
    for (int i = 0; i < 7; i++) {   // M^128
        float na = a * a + b * cc;
        float nb = a * b + b * d;
        float nc = cc * a + d * cc;
        float nd = cc * b + d * d;
        a = na; b = nb; cc = nc; d = nd;
    }

    float2 f = g_final[c * NSEQ + seq];
    float ma = a, mb = b, mc = cc, md = d;
    float f1 = f.x, f2 = f.y;

    __shared__ float sa[NCHUNK], sb[NCHUNK], sc[NCHUNK], sd[NCHUNK];
    __shared__ float s1[NCHUNK], s2[NCHUNK];

    #pragma unroll
    for (int dstep = 1; dstep < NCHUNK; dstep <<= 1) {
        sa[c] = ma; sb[c] = mb; sc[c] = mc; sd[c] = md; s1[c] = f1; s2[c] = f2;
        __syncthreads();
        if (c >= dstep) {
            int j = c - dstep;
            float pa = sa[j], pb = sb[j], pc = sc[j], pd = sd[j];
            float p1 = s1[j], p2 = s2[j];
            float nf1 = ma * p1 + mb * p2 + f1;
            float nf2 = mc * p1 + md * p2 + f2;
            float na = ma * pa + mb * pc;
            float nb = ma * pb + mb * pd;
            float nc = mc * pa + md * pc;
            float nd = mc * pb + md * pd;
            ma = na; mb = nb; mc = nc; md = nd; f1 = nf1; f2 = nf2;
        }
        __syncthreads();
    }
    s1[c] = f1; s2[c] = f2;
    __syncthreads();
    float i1 = (c == 0) ? 0.0f : s1[c - 1];
    float i2 = (c == 0) ? 0.0f : s2[c - 1];
    g_initv[c * NSEQ + seq] = make_float2(i1, i2);
}

// Pass C: re-run chunk scans (2 seqs/thread); emit x2 split bf16 pairs, permuted.
__global__ void scan_passC(const float* __restrict__ A_diag, const float* __restrict__ steps) {
    int t = threadIdx.x;               // 0..255 ; handles seqs 2t, 2t+1
    int c = blockIdx.x;
    int s0 = 2 * t, s1 = 2 * t + 1;
    float a11, a12, a21, a22, ac1, ac2;
    float b11, b12, b21, b22, bc1, bc2;
    get_consts(A_diag, steps, s0 & (P_DIM - 1), a11, a12, a21, a22, ac1, ac2);
    get_consts(A_diag, steps, s1 & (P_DIM - 1), b11, b12, b21, b22, bc1, bc2);

    float2 i0 = g_initv[c * NSEQ + s0];
    float2 i1 = g_initv[c * NSEQ + s1];
    float x1a = i0.x, x2a = i0.y, x1b = i1.x, x2b = i1.y;

    int col = pair_pos(t);             // pair index t over 256 pairs (K=512)
    const float* bu = g_buall + (size_t)c * CLEN * NSEQ + s0;
    uint32_t* xh = g_x2H + (size_t)c * CLEN * 256 + col;
    uint32_t* xl = g_x2L + (size_t)c * CLEN * 256 + col;

    #pragma unroll 4
    for (int s = 0; s < CLEN; s++) {
        float2 u = *reinterpret_cast<const float2*>(bu + (size_t)s * NSEQ);
        float n1a = fmaf(a11, x1a, fmaf(a12, x2a, ac1 * u.x));
        float n2a = fmaf(a21, x1a, fmaf(a22, x2a, ac2 * u.x));
        float n1b = fmaf(b11, x1b, fmaf(b12, x2b, bc1 * u.y));
        float n2b = fmaf(b21, x1b, fmaf(b22, x2b, bc2 * u.y));
        x1a = n1a; x2a = n2a; x1b = n1b; x2b = n2b;
        float h0 = bfhi(x2a), h1 = bfhi(x2b);
        xh[(size_t)s * 256] = packbf(h0, h1);
        xl[(size_t)s * 256] = packbf(x2a - h0, x2b - h1);
    }
}

// ---------------------------------------------------------------------------
extern "C" void kernel_launch(void* const* d_in, const int* in_sizes, int n_in,
                              void* d_out, int out_size) {
    const float* input  = (const float*)d_in[0];  // (L, H)
    const float* A_diag = (const float*)d_in[1];  // (P,)
    const float* B      = (const float*)d_in[2];  // (P, H, 2)
    const float* C      = (const float*)d_in[3];  // (H, P, 2)
    const float* D      = (const float*)d_in[4];  // (H,)
    const float* steps  = (const float*)d_in[5];  // (P,)
    float* out = (float*)d_out;                   // (L, H)

    float *p_bu;
    uint32_t *p_inH, *p_inL, *p_w1H, *p_w1L, *p_w2H, *p_w2L, *p_x2H, *p_x2L;
    cudaGetSymbolAddress((void**)&p_bu,  g_buall);
    cudaGetSymbolAddress((void**)&p_inH, g_inH);
    cudaGetSymbolAddress((void**)&p_inL, g_inL);
    cudaGetSymbolAddress((void**)&p_w1H, g_W1H);
    cudaGetSymbolAddress((void**)&p_w1L, g_W1L);
    cudaGetSymbolAddress((void**)&p_w2H, g_W2H);
    cudaGetSymbolAddress((void**)&p_w2L, g_W2L);
    cudaGetSymbolAddress((void**)&p_x2H, g_x2H);
    cudaGetSymbolAddress((void**)&p_x2L, g_x2L);

    const int dyn = STAGE_U * 2 * sizeof(uint32_t);   // 49152 bytes
    cudaFuncSetAttribute(gemm_bf16x3<true, false>,
                         cudaFuncAttributeMaxDynamicSharedMemorySize, dyn);
    cudaFuncSetAttribute(gemm_bf16x3<false, true>,
                         cudaFuncAttributeMaxDynamicSharedMemorySize, dyn);

    prep_input<<<L_SEQ * 64 / 256, 256>>>(input);
    prep_w<<<128, 256>>>(B, C);

    // GEMM1 + fused passA: Bu = input @ W1^T  (16384 x 512, K=128)
    gemm_bf16x3<true, false><<<dim3(NSEQ / 64, L_SEQ / 128), 256, dyn>>>(
        p_inH, p_inL, p_w1H, p_w1L, p_bu, L_SEQ, NSEQ, H_DIM,
        nullptr, nullptr, A_diag, steps);

    scan_passB_par<<<NSEQ, NCHUNK>>>(A_diag, steps);
    scan_passC<<<NCHUNK, 256>>>(A_diag, steps);

    // GEMM2: ys = x2 @ W2^T + input * D  (16384 x 128, K=512)
    gemm_bf16x3<false, true><<<dim3(H_DIM / 64, L_SEQ / 128), 256, dyn>>>(
        p_x2H, p_x2L, p_w2H, p_w2L, out, L_SEQ, H_DIM, NSEQ,
        input, D, nullptr, nullptr);
}